// round 7
// baseline (speedup 1.0000x reference)
#include <cuda_runtime.h>
#include <cuda_bf16.h>
#include <cstdint>

// ALiBi bias add: out[b,h,i,j] = scores[b,h,i,j] + (j - i) * slopes[h]
// Streaming, HBM-bound (measured plateau ~6.8 TB/s). 2x float4 per thread
// (front-batched), evict-first (.cs) hints, 256-thread blocks for max
// occupancy, shift/mask index math on the pow2 fast path (S=2048, H=16).

__device__ __forceinline__ void alibi_idx(unsigned e, unsigned S, unsigned H,
                                          float& d0, unsigned& h) {
    unsigned j, row, i, hb;
    if ((S & (S - 1u)) == 0u) {
        const unsigned sh = 31u - (unsigned)__clz((int)S);
        const unsigned m  = S - 1u;
        j   = e & m;
        row = e >> sh;
        i   = row & m;
        hb  = row >> sh;
    } else {
        j   = e % S;
        row = e / S;
        i   = row % S;
        hb  = row / S;
    }
    h  = ((H & (H - 1u)) == 0u) ? (hb & (H - 1u)) : (hb % H);
    d0 = (float)((int)j - (int)i);
}

__device__ __forceinline__ float4 alibi_apply(float4 v, float d, float s) {
    v.x = fmaf(d,        s, v.x);
    v.y = fmaf(d + 1.0f, s, v.y);
    v.z = fmaf(d + 2.0f, s, v.z);
    v.w = fmaf(d + 3.0f, s, v.w);
    return v;
}

__global__ __launch_bounds__(256)
void alibi_vec4x2_cs256_kernel(const float4* __restrict__ in,
                               const float*  __restrict__ slopes,
                               const int*    __restrict__ seq_len,
                               float4*       __restrict__ out,
                               unsigned n4, unsigned half, unsigned H) {
    const unsigned t = blockIdx.x * blockDim.x + threadIdx.x;
    if (t >= half) return;

    const unsigned S = (unsigned)__ldg(seq_len);  // uniform; L2-resident

    const unsigned i0 = t;
    const unsigned i1 = t + half;
    const bool has1  = (i1 < n4);
    const unsigned i1c = has1 ? i1 : (n4 - 1u);   // clamp: keep load unpredicated

    // Front-batched evict-first loads (streaming data, zero reuse)
    float4 v0 = __ldcs(&in[i0]);
    float4 v1 = __ldcs(&in[i1c]);

    float d; unsigned h;

    alibi_idx(i0 << 2, S, H, d, h);
    __stcs(&out[i0], alibi_apply(v0, d, __ldg(&slopes[h])));

    if (has1) {
        alibi_idx(i1 << 2, S, H, d, h);
        __stcs(&out[i1], alibi_apply(v1, d, __ldg(&slopes[h])));
    }
}

// Scalar tail for n % 4 != 0 (not hit for S=2048, kept for shape variants).
__global__ void alibi_tail_kernel(const float* __restrict__ in,
                                  const float* __restrict__ slopes,
                                  const int*   __restrict__ seq_len,
                                  float*       __restrict__ out,
                                  unsigned base, unsigned n, unsigned H) {
    unsigned idx = base + blockIdx.x * blockDim.x + threadIdx.x;
    if (idx >= n) return;
    const unsigned S = (unsigned)__ldg(seq_len);
    unsigned j   = idx % S;
    unsigned row = idx / S;
    unsigned i   = row % S;
    unsigned h   = (row / S) % H;
    out[idx] = fmaf((float)((int)j - (int)i), slopes[h], in[idx]);
}

extern "C" void kernel_launch(void* const* d_in, const int* in_sizes, int n_in,
                              void* d_out, int out_size) {
    const float4* in     = (const float4*)d_in[0];
    const float*  slopes = (const float*)d_in[1];
    const int*    seq    = (const int*)d_in[2];
    float4*       out    = (float4*)d_out;

    const unsigned n    = (unsigned)in_sizes[0];
    const unsigned H    = (unsigned)in_sizes[1];
    const unsigned n4   = n >> 2;
    const unsigned half = (n4 + 1u) >> 1;

    if (half > 0) {
        const unsigned threads = 256;
        const unsigned blocks  = (half + threads - 1) / threads;
        alibi_vec4x2_cs256_kernel<<<blocks, threads>>>(in, slopes, seq, out, n4, half, H);
    }

    const unsigned tail = n & 3u;
    if (tail) {
        alibi_tail_kernel<<<1, 32>>>((const float*)d_in[0], slopes, seq,
                                     (float*)d_out, n4 << 2, n, H);
    }
}

// round 16
// speedup vs baseline: 1.0049x; 1.0049x over previous
#include <cuda_runtime.h>
#include <cuda_bf16.h>
#include <cstdint>

// ALiBi bias add: out[b,h,i,j] = scores[b,h,i,j] + (j - i) * slopes[h]
// Streaming, HBM-bound (measured plateau ~6.8 TB/s = chip streaming ceiling).
// Best measured config: 512-thread blocks, 2x float4 per thread
// (front-batched), evict-first (.cs) hints, shift/mask index math on the
// pow2 fast path (S=2048, H=16), 32-bit div fallback for odd shapes.

__device__ __forceinline__ void alibi_idx(unsigned e, unsigned S, unsigned H,
                                          float& d0, unsigned& h) {
    unsigned j, row, i, hb;
    if ((S & (S - 1u)) == 0u) {
        const unsigned sh = 31u - (unsigned)__clz((int)S);
        const unsigned m  = S - 1u;
        j   = e & m;
        row = e >> sh;
        i   = row & m;
        hb  = row >> sh;
    } else {
        j   = e % S;
        row = e / S;
        i   = row % S;
        hb  = row / S;
    }
    h  = ((H & (H - 1u)) == 0u) ? (hb & (H - 1u)) : (hb % H);
    d0 = (float)((int)j - (int)i);
}

__device__ __forceinline__ float4 alibi_apply(float4 v, float d, float s) {
    v.x = fmaf(d,        s, v.x);
    v.y = fmaf(d + 1.0f, s, v.y);
    v.z = fmaf(d + 2.0f, s, v.z);
    v.w = fmaf(d + 3.0f, s, v.w);
    return v;
}

__global__ __launch_bounds__(512)
void alibi_vec4x2_cs_kernel(const float4* __restrict__ in,
                            const float*  __restrict__ slopes,
                            const int*    __restrict__ seq_len,
                            float4*       __restrict__ out,
                            unsigned n4, unsigned half, unsigned H) {
    const unsigned t = blockIdx.x * blockDim.x + threadIdx.x;
    if (t >= half) return;

    const unsigned S = (unsigned)__ldg(seq_len);  // uniform; L2-resident

    const unsigned i0 = t;
    const unsigned i1 = t + half;
    const bool has1  = (i1 < n4);
    const unsigned i1c = has1 ? i1 : (n4 - 1u);   // clamp: keep load unpredicated

    // Front-batched evict-first loads (streaming data, zero reuse)
    float4 v0 = __ldcs(&in[i0]);
    float4 v1 = __ldcs(&in[i1c]);

    float d; unsigned h;

    alibi_idx(i0 << 2, S, H, d, h);
    __stcs(&out[i0], alibi_apply(v0, d, __ldg(&slopes[h])));

    if (has1) {
        alibi_idx(i1 << 2, S, H, d, h);
        __stcs(&out[i1], alibi_apply(v1, d, __ldg(&slopes[h])));
    }
}

// Scalar tail for n % 4 != 0 (not hit for S=2048, kept for shape variants).
__global__ void alibi_tail_kernel(const float* __restrict__ in,
                                  const float* __restrict__ slopes,
                                  const int*   __restrict__ seq_len,
                                  float*       __restrict__ out,
                                  unsigned base, unsigned n, unsigned H) {
    unsigned idx = base + blockIdx.x * blockDim.x + threadIdx.x;
    if (idx >= n) return;
    const unsigned S = (unsigned)__ldg(seq_len);
    unsigned j   = idx % S;
    unsigned row = idx / S;
    unsigned i   = row % S;
    unsigned h   = (row / S) % H;
    out[idx] = fmaf((float)((int)j - (int)i), slopes[h], in[idx]);
}

extern "C" void kernel_launch(void* const* d_in, const int* in_sizes, int n_in,
                              void* d_out, int out_size) {
    const float4* in     = (const float4*)d_in[0];
    const float*  slopes = (const float*)d_in[1];
    const int*    seq    = (const int*)d_in[2];
    float4*       out    = (float4*)d_out;

    const unsigned n    = (unsigned)in_sizes[0];
    const unsigned H    = (unsigned)in_sizes[1];
    const unsigned n4   = n >> 2;
    const unsigned half = (n4 + 1u) >> 1;

    if (half > 0) {
        const unsigned threads = 512;
        const unsigned blocks  = (half + threads - 1) / threads;
        alibi_vec4x2_cs_kernel<<<blocks, threads>>>(in, slopes, seq, out, n4, half, H);
    }

    const unsigned tail = n & 3u;
    if (tail) {
        alibi_tail_kernel<<<1, 32>>>((const float*)d_in[0], slopes, seq,
                                     (float*)d_out, n4 << 2, n, H);
    }
}